// round 6
// baseline (speedup 1.0000x reference)
#include <cuda_runtime.h>

// LSTM: B x T x I -> last hidden -> FC.  I=4, H=8, O=1, T=512.
// Round-6: 4 lanes per batch element (lane owns hidden units 2l, 2l+1).
// A warp carries 8 batch elements -> the 8 SHFLs broadcasting h serve 8
// batches (half the per-batch MIO cost of round 4). k-pair f32x2 packing:
// x float4 bitcasts to two u64 pairs, h arrives as shuffled u64 pairs, so
// zero dup/pack movs in the hot path. Kept: tanh.approx, folded 0.5 sigmoid
// scales, 4-deep x prefetch. 1024 warps (1.73/SMSP).

#define T_SEQ 512
#define IDIM  4
#define HDIM  8

typedef unsigned long long u64;

__device__ __forceinline__ u64 pack2(float a, float b) {
    u64 r; asm("mov.b64 %0,{%1,%2};" : "=l"(r) : "f"(a), "f"(b)); return r;
}
__device__ __forceinline__ float2 unpack2(u64 v) {
    float2 r; asm("mov.b64 {%0,%1},%2;" : "=f"(r.x), "=f"(r.y) : "l"(v)); return r;
}
__device__ __forceinline__ u64 fma2(u64 a, u64 b, u64 c) {
    u64 d; asm("fma.rn.f32x2 %0,%1,%2,%3;" : "=l"(d) : "l"(a), "l"(b), "l"(c)); return d;
}
__device__ __forceinline__ float hadd2(u64 v) {
    float2 t = unpack2(v); return t.x + t.y;
}
__device__ __forceinline__ float tanh_fast(float x) {
    float y; asm("tanh.approx.f32 %0,%1;" : "=f"(y) : "f"(x)); return y;
}
__device__ __forceinline__ float sig_half(float zhalf) {   // z pre-scaled by 0.5
    return fmaf(0.5f, tanh_fast(zhalf), 0.5f);
}

// 8 gate rows per lane: r = gate*2 + s, gate in {i,f,g,o}, s in {0,1} = unit 2l+s
struct LaneW {
    u64 wih[8][2];    // input weights, k-paired
    u64 whh[8][4];    // recurrent weights, k-paired
    u64 bias[8];      // (bias, 0)
};

__global__ __launch_bounds__(32)
void lstm_fused_kernel(const float* __restrict__ x,
                       const float* __restrict__ W_ih,
                       const float* __restrict__ W_hh,
                       const float* __restrict__ b_ih,
                       const float* __restrict__ b_hh,
                       const float* __restrict__ W_fc,
                       const float* __restrict__ b_fc,
                       float* __restrict__ out,
                       int B)
{
    const int tid = threadIdx.x;
    const int l   = tid & 3;                         // lane within 4-lane group
    int b = blockIdx.x * 8 + (tid >> 2);             // batch element (8 groups/warp)
    const bool valid = (b < B);
    if (b >= B) b = B - 1;                           // clamp: keep warp converged

    // ---- per-lane weights; sigmoid rows (i,f,o) pre-scaled by 0.5 ----
    LaneW W;
#pragma unroll
    for (int g = 0; g < 4; ++g) {
        const float s = (g == 2) ? 1.0f : 0.5f;
#pragma unroll
        for (int su = 0; su < 2; ++su) {
            const int r   = g * 2 + su;
            const int row = g * HDIM + 2 * l + su;
#pragma unroll
            for (int m = 0; m < 2; ++m)
                W.wih[r][m] = pack2(s * W_ih[row * IDIM + 2 * m],
                                    s * W_ih[row * IDIM + 2 * m + 1]);
#pragma unroll
            for (int m = 0; m < 4; ++m)
                W.whh[r][m] = pack2(s * W_hh[row * HDIM + 2 * m],
                                    s * W_hh[row * HDIM + 2 * m + 1]);
            W.bias[r] = pack2(s * (b_ih[row] + b_hh[row]), 0.0f);
        }
    }

    const float4* __restrict__ xp =
        reinterpret_cast<const float4*>(x) + (size_t)b * T_SEQ;

    float h0 = 0.0f, h1 = 0.0f;          // this lane's two hidden units
    float c0 = 0.0f, c1 = 0.0f;
    u64 hp = 0;                          // packed (h0,h1) for exchange

    // rolling 4-step prefetch buffer (covers DRAM miss latency, MLP=4)
    float4 buf0 = xp[0], buf1 = xp[1], buf2 = xp[2], buf3 = xp[3];

#pragma unroll 1
    for (int t0 = 0; t0 < T_SEQ; t0 += 4) {
        const int tn = (t0 + 4) & (T_SEQ - 1);       // wraps on last iter (harmless)
        const float4 n0 = xp[tn + 0];
        const float4 n1 = xp[tn + 1];
        const float4 n2 = xp[tn + 2];
        const float4 n3 = xp[tn + 3];

        const float4 bufs[4] = {buf0, buf1, buf2, buf3};
#pragma unroll
        for (int u = 0; u < 4; ++u) {
            const float4 xc = bufs[u];
            const u64 x01 = pack2(xc.x, xc.y);
            const u64 x23 = pack2(xc.z, xc.w);

            // ---- input projection + bias (h-independent) ----
            u64 acc[8];
#pragma unroll
            for (int r = 0; r < 8; ++r) {
                u64 a  = fma2(W.wih[r][0], x01, W.bias[r]);
                acc[r] = fma2(W.wih[r][1], x23, a);
            }

            // ---- broadcast h pairs within the 4-lane group (8 SHFL / 8 batches) ----
            const u64 hb0 = __shfl_sync(0xffffffffu, hp, 0, 4);   // (h0,h1)
            const u64 hb1 = __shfl_sync(0xffffffffu, hp, 1, 4);   // (h2,h3)
            const u64 hb2 = __shfl_sync(0xffffffffu, hp, 2, 4);   // (h4,h5)
            const u64 hb3 = __shfl_sync(0xffffffffu, hp, 3, 4);   // (h6,h7)

            // ---- recurrent projection ----
#pragma unroll
            for (int r = 0; r < 8; ++r) {
                u64 a = fma2(W.whh[r][0], hb0, acc[r]);
                a     = fma2(W.whh[r][1], hb1, a);
                a     = fma2(W.whh[r][2], hb2, a);
                acc[r]= fma2(W.whh[r][3], hb3, a);
            }

            // ---- activations + state update (2 units) ----
            const float zi0 = hadd2(acc[0]), zi1 = hadd2(acc[1]);
            const float zf0 = hadd2(acc[2]), zf1 = hadd2(acc[3]);
            const float zg0 = hadd2(acc[4]), zg1 = hadd2(acc[5]);
            const float zo0 = hadd2(acc[6]), zo1 = hadd2(acc[7]);

            const float ig0 = sig_half(zi0),  ig1 = sig_half(zi1);
            const float fg0 = sig_half(zf0),  fg1 = sig_half(zf1);
            const float gg0 = tanh_fast(zg0), gg1 = tanh_fast(zg1);
            const float og0 = sig_half(zo0),  og1 = sig_half(zo1);

            c0 = fmaf(fg0, c0, ig0 * gg0);
            c1 = fmaf(fg1, c1, ig1 * gg1);
            h0 = og0 * tanh_fast(c0);
            h1 = og1 * tanh_fast(c1);
            hp = pack2(h0, h1);
        }

        buf0 = n0; buf1 = n1; buf2 = n2; buf3 = n3;
    }

    // ---- FC head: out[b] = sum_j h_j * W_fc[j] + b_fc ----
    float v = h0 * __ldg(W_fc + 2 * l) + h1 * __ldg(W_fc + 2 * l + 1);
    v += __shfl_xor_sync(0xffffffffu, v, 1, 4);
    v += __shfl_xor_sync(0xffffffffu, v, 2, 4);

    if (valid && l == 0) out[b] = v + __ldg(b_fc);
}

extern "C" void kernel_launch(void* const* d_in, const int* in_sizes, int n_in,
                              void* d_out, int out_size)
{
    const float* x    = (const float*)d_in[0];
    const float* W_ih = (const float*)d_in[1];
    const float* W_hh = (const float*)d_in[2];
    const float* b_ih = (const float*)d_in[3];
    const float* b_hh = (const float*)d_in[4];
    const float* W_fc = (const float*)d_in[5];
    const float* b_fc = (const float*)d_in[6];
    float* out = (float*)d_out;

    const int B = in_sizes[0] / (T_SEQ * IDIM);      // 8192 here
    const int groups_per_block = 8;                  // 32 threads / 4 lanes
    const int grid = (B + groups_per_block - 1) / groups_per_block;

    lstm_fused_kernel<<<grid, 32>>>(x, W_ih, W_hh, b_ih, b_hh, W_fc, b_fc, out, B);
}